// round 14
// baseline (speedup 1.0000x reference)
#include <cuda_runtime.h>
#include <cuda_bf16.h>
#include <mma.h>
using namespace nvcuda;

#define BS_ 1024
#define DS_ 128
#define DM_ 256
#define NH_ 4
#define DH_ 32
#define T_ 8
#define NL_ 2
#define VOC_ 32000
#define DECAY_F 0.6065306597126334f
#define SCALE_F 0.17677669529663687f

// ---------------- device state ----------------
__device__ __align__(16) float g_tok[BS_*DM_];
__device__ __align__(16) float g_x[BS_*DM_];
__device__ __align__(16) float g_hbuf[NL_][2][BS_*DS_];
__device__ __align__(16) float g_sv[NL_][BS_*DS_];
__device__ __align__(16) float g_ov[NL_][BS_*DM_];
__device__ __align__(16) float g_kv0[BS_*2*DS_];
__device__ __align__(16) float g_kv[BS_*2*DS_];
__device__ __align__(16) float g_att[BS_*DS_];
__device__ __align__(16) float g_tsum[BS_*DM_];
// transposed weights
__device__ __align__(16) float g_Wqt[NL_][DS_*DS_];
__device__ __align__(16) float g_At [NL_][DS_*DS_];
__device__ __align__(16) float g_Wot[NL_][DS_*DS_];
__device__ __align__(16) float g_Ct [NL_][DS_*DM_];
__device__ __align__(16) float g_Wkvt[NL_][DM_*2*DS_];
__device__ float g_ts[NL_], g_to[NL_];
__device__ unsigned int g_cnt1, g_cnt2;

// score-factorization buffers: R[head][k][b], c[head][b]
__device__ __align__(16) float g_Rt0[NH_][DS_][BS_];
__device__ __align__(16) float g_Rt1[NH_][DS_][BS_];
__device__ float g_c0[NH_][BS_];
__device__ float g_c1[NH_][BS_];

// bf16 split storage for logits
__device__ __align__(16) __nv_bfloat16 g_Whi[(size_t)VOC_*DM_];
__device__ __align__(16) __nv_bfloat16 g_Wlo[(size_t)VOC_*DM_];
__device__ __align__(16) __nv_bfloat16 g_Bext[(size_t)VOC_*32];

// ---------------- fused setup ----------------
__global__ void setup_kernel(const int* __restrict__ ids, const float* __restrict__ emb,
                             const float* __restrict__ Wq, const float* __restrict__ Amat,
                             const float* __restrict__ Wo, const float* __restrict__ Cmat,
                             const float* __restrict__ Wkv,
                             const float* __restrict__ Wout, const float* __restrict__ bout) {
    int idx = blockIdx.x * blockDim.x + threadIdx.x;
    int stride = gridDim.x * blockDim.x;
    {
        float* h  = &g_hbuf[0][0][0];
        float* sv = &g_sv[0][0];
        float* ov = &g_ov[0][0];
        for (int i = idx; i < NL_*2*BS_*DS_; i += stride) h[i] = 0.f;
        for (int i = idx; i < NL_*BS_*DS_;  i += stride) sv[i] = 0.f;
        for (int i = idx; i < NL_*BS_*DM_;  i += stride) ov[i] = 0.f;
        for (int i = idx; i < BS_*DM_;      i += stride) g_tsum[i] = 0.f;
        if (idx == 0) {
            g_ts[0] = g_ts[1] = 1.0f;
            g_to[0] = g_to[1] = 1.0f;
            g_cnt1 = 0u; g_cnt2 = 0u;
        }
    }
    for (int i = idx; i < BS_*DM_; i += stride) {
        int row = i >> 8, j = i & 255;
        g_tok[i] = emb[(size_t)ids[row]*DM_ + j];
    }
    for (int i = idx; i < NL_*DS_*DS_; i += stride) {
        int l = i / (DS_*DS_), rem = i % (DS_*DS_);
        int k = rem / DS_, d = rem % DS_;
        g_Wqt[l][rem] = Wq[l*DS_*DS_ + d*DS_ + k];
        g_At [l][rem] = Amat[l*DS_*DS_ + d*DS_ + k];
        g_Wot[l][rem] = Wo[l*DS_*DS_ + d*DS_ + k];
    }
    for (int i = idx; i < NL_*DS_*DM_; i += stride) {
        int l = i / (DS_*DM_), rem = i % (DS_*DM_);
        int k = rem / DM_, c = rem % DM_;
        g_Ct[l][rem] = Cmat[l*DM_*DS_ + c*DS_ + k];
    }
    for (int i = idx; i < NL_*DM_*2*DS_; i += stride) {
        int l = i / (DM_*2*DS_), rem = i % (DM_*2*DS_);
        int k = rem / (2*DS_), c = rem % (2*DS_);
        g_Wkvt[l][rem] = Wkv[l*2*DS_*DM_ + c*DM_ + k];
    }
    {
        const int tot4 = VOC_ * DM_ / 4;
        for (int i = idx; i < tot4; i += stride) {
            float4 w = reinterpret_cast<const float4*>(Wout)[i];
            __nv_bfloat16 hb[4], lb[4];
            hb[0] = __float2bfloat16(w.x); lb[0] = __float2bfloat16(w.x - __bfloat162float(hb[0]));
            hb[1] = __float2bfloat16(w.y); lb[1] = __float2bfloat16(w.y - __bfloat162float(hb[1]));
            hb[2] = __float2bfloat16(w.z); lb[2] = __float2bfloat16(w.z - __bfloat162float(hb[2]));
            hb[3] = __float2bfloat16(w.w); lb[3] = __float2bfloat16(w.w - __bfloat162float(hb[3]));
            reinterpret_cast<uint2*>(g_Whi)[i] = *reinterpret_cast<uint2*>(hb);
            reinterpret_cast<uint2*>(g_Wlo)[i] = *reinterpret_cast<uint2*>(lb);
        }
        for (int n = idx; n < VOC_; n += stride) {
            float b = bout[n];
            __nv_bfloat16 buf[16];
            buf[0] = __float2bfloat16(b);
            buf[1] = __float2bfloat16(b - __bfloat162float(buf[0]));
#pragma unroll
            for (int c = 2; c < 16; c++) buf[c] = __float2bfloat16(0.f);
            uint4* dst = reinterpret_cast<uint4*>(&g_Bext[(size_t)n*32]);
            dst[0] = reinterpret_cast<uint4*>(buf)[0];
            dst[1] = reinterpret_cast<uint4*>(buf)[1];
            uint4 z; z.x = z.y = z.z = z.w = 0u;
            dst[2] = z; dst[3] = z;
        }
    }
}

// ---------------- dense kv for layer 0 (once) ----------------
__global__ void __launch_bounds__(512)
k_kv0(const float* __restrict__ Wkv, const float* __restrict__ bkv) {
    __shared__ __align__(16) float As[16][64];
    __shared__ __align__(16) float Ws[16][64];
    const int tid = threadIdx.x;
    const int row0 = blockIdx.y*64, col0 = blockIdx.x*64;
    const int ty = tid >> 4;
    const int tx = tid & 15;
    float acc[2][4] = {};
    for (int k0 = 0; k0 < DM_; k0 += 16) {
        if (tid < 256) {
            int lr = tid >> 2, lk = (tid & 3) << 2;
            float4 av = *reinterpret_cast<const float4*>(g_tok + (size_t)(row0+lr)*DM_ + k0 + lk);
            As[lk+0][lr]=av.x; As[lk+1][lr]=av.y; As[lk+2][lr]=av.z; As[lk+3][lr]=av.w;
        } else {
            int t2 = tid - 256;
            int lr = t2 >> 2, lk = (t2 & 3) << 2;
            float4 wv = *reinterpret_cast<const float4*>(Wkv + (size_t)(col0+lr)*DM_ + k0 + lk);
            Ws[lk+0][lr]=wv.x; Ws[lk+1][lr]=wv.y; Ws[lk+2][lr]=wv.z; Ws[lk+3][lr]=wv.w;
        }
        __syncthreads();
#pragma unroll
        for (int kk = 0; kk < 16; kk++) {
            float2 a = *reinterpret_cast<const float2*>(&As[kk][ty*2]);
            float4 w = *reinterpret_cast<const float4*>(&Ws[kk][tx*4]);
            acc[0][0]+=a.x*w.x; acc[0][1]+=a.x*w.y; acc[0][2]+=a.x*w.z; acc[0][3]+=a.x*w.w;
            acc[1][0]+=a.y*w.x; acc[1][1]+=a.y*w.y; acc[1][2]+=a.y*w.z; acc[1][3]+=a.y*w.w;
        }
        __syncthreads();
    }
#pragma unroll
    for (int i = 0; i < 2; i++) {
        int r = row0 + ty*2 + i;
#pragma unroll
        for (int j = 0; j < 4; j++) {
            int c = col0 + tx*4 + j;
            g_kv0[r*(2*DS_) + c] = acc[i][j] + bkv[c];
        }
    }
}

// ---------------- R factor ----------------
__global__ void __launch_bounds__(512)
k_rt(int l, const float* __restrict__ bq) {
    __shared__ __align__(16) float Ks[64][33];
    __shared__ __align__(16) float Wqs[32][128];
    const int tid = threadIdx.x;
    const int b0 = blockIdx.x * 64;
    const int head = blockIdx.y;
    const int hd = head * DH_;
    const float* kvsrc = (l == 0) ? g_kv0 : g_kv;
    float* Rt = (l == 0) ? &g_Rt0[head][0][0] : &g_Rt1[head][0][0];
    float* cv = (l == 0) ? g_c0[head] : g_c1[head];

    {
        int b = tid >> 3, d4 = (tid & 7) * 4;
        float4 v = *reinterpret_cast<const float4*>(kvsrc + (size_t)(b0+b)*(2*DS_) + hd + d4);
        Ks[b][d4] = v.x; Ks[b][d4+1] = v.y; Ks[b][d4+2] = v.z; Ks[b][d4+3] = v.w;
    }
    for (int i = tid; i < 32*128; i += 512) {
        int d = i >> 7, k = i & 127;
        Wqs[d][k] = g_Wqt[l][k*DS_ + hd + d];
    }
    __syncthreads();
    const int w = tid >> 5, lane = tid & 31;
    const int bloc = lane * 2;
    float acc[8][2] = {};
    for (int d = 0; d < 32; d++) {
        float kb0 = Ks[bloc][d], kb1 = Ks[bloc+1][d];
        const float* wq = &Wqs[d][w*8];
#pragma unroll
        for (int j = 0; j < 8; j++) {
            float q = wq[j];
            acc[j][0] += q * kb0;
            acc[j][1] += q * kb1;
        }
    }
#pragma unroll
    for (int j = 0; j < 8; j++) {
        float2 st = make_float2(acc[j][0], acc[j][1]);
        *reinterpret_cast<float2*>(Rt + (size_t)(w*8+j)*BS_ + b0 + bloc) = st;
    }
    if (tid < 64) {
        float cc = 0.f;
#pragma unroll
        for (int d = 0; d < 32; d++)
            cc += bq[l*DS_ + hd + d] * Ks[tid][d];
        cv[b0 + tid] = cc;
    }
}

// ---------------- attention: gathered scores + 256-thread PV (2 rows x 2 dims) ----------------
__global__ void __launch_bounds__(512)
k_attn2(int l, int prev_l, int par) {
    __shared__ __align__(16) float Vs[128][36];
    __shared__ __align__(16) float Ps[32][132];
    __shared__ float corrs[32], invs[32];
    __shared__ short ql[32][128];
    __shared__ int qcnt[32];
    const int tid = threadIdx.x;
    const int head = blockIdx.y;
    const int q0 = blockIdx.x * 32;
    const float* kvsrc = (l == 0) ? g_kv0 : g_kv;
    const float* hsrc = g_hbuf[l][par];
    const float* Rt = (l == 0) ? &g_Rt0[head][0][0] : &g_Rt1[head][0][0];
    const float* cv = (l == 0) ? g_c0[head] : g_c1[head];
    const int hd = head * DH_;

    if (prev_l >= 0 && blockIdx.x == 0 && blockIdx.y == 0 && tid == 0) {
        float e1 = (float)g_cnt1 / (float)(BS_*DS_) - 0.02f;
        g_ts[prev_l] = fmaxf(g_ts[prev_l] + 0.1f*e1, 0.5f);
        float e2 = (float)g_cnt2 / (float)(BS_*DM_) - 0.02f;
        g_to[prev_l] = fmaxf(g_to[prev_l] + 0.1f*e2, 0.5f);
        g_cnt1 = 0u; g_cnt2 = 0u;
    }

    // sparse lists: 16 warps x 2 rows
    {
        const int wrp = tid >> 5, lane = tid & 31;
#pragma unroll
        for (int rr = 0; rr < 2; rr++) {
            int r = wrp*2 + rr;
            int base = 0;
            const float* hr = hsrc + (size_t)(q0+r)*DS_;
#pragma unroll
            for (int c4 = 0; c4 < 4; c4++) {
                float v = hr[c4*32 + lane];
                unsigned mask = __ballot_sync(0xffffffffu, v != 0.f);
                if (v != 0.f)
                    ql[r][base + __popc(mask & ((1u<<lane)-1u))] = (short)(c4*32 + lane);
                base += __popc(mask);
            }
            if (lane == 0) qcnt[r] = base;
        }
    }
    __syncthreads();

    const int r = tid >> 4;            // softmax row
    const int lane = tid & 15;
    const int cnt = qcnt[r];

    // PV mapping: threads 0..255, 2 rows x 2 dims each
    const bool pv_on = (tid < 256);
    const int pr0 = (tid >> 4) * 2;    // rows pr0..pr0+1 (0..30)
    const int pd0 = (tid & 15) * 2;

    float m = -INFINITY, lsum = 0.f;
    float oa[2][2] = {}, ob[2][2] = {};

    for (int kt = 0; kt < 8; kt++) {
        __syncthreads();
        // stage V: 128 rows x 32 dims
#pragma unroll
        for (int u = 0; u < 2; u++) {
            int i = tid + u*512;
            int kr = i >> 3, d4 = (i & 7) * 4;
            int key = kt*128 + kr;
            float4 v = *reinterpret_cast<const float4*>(kvsrc + (size_t)key*(2*DS_) + DS_ + hd + d4);
            Vs[kr][d4] = v.x; Vs[kr][d4+1] = v.y; Vs[kr][d4+2] = v.z; Vs[kr][d4+3] = v.w;
        }
        // gathered scores: 8 keys per lane
        const int kb = kt*128 + lane;
        float s8[8];
#pragma unroll
        for (int kk = 0; kk < 8; kk++) s8[kk] = cv[kb + kk*16];
        for (int i2 = 0; i2 < cnt; i2++) {
            const float* rp = Rt + (size_t)ql[r][i2]*BS_ + kb;
#pragma unroll
            for (int kk = 0; kk < 8; kk++) s8[kk] += rp[kk*16];
        }
        // online softmax
        float tmax = -INFINITY;
#pragma unroll
        for (int kk = 0; kk < 8; kk++) { s8[kk] *= SCALE_F; tmax = fmaxf(tmax, s8[kk]); }
#pragma unroll
        for (int off = 8; off > 0; off >>= 1)
            tmax = fmaxf(tmax, __shfl_xor_sync(0xffffffffu, tmax, off));
        float mnew = fmaxf(m, tmax);
        float corr = __expf(m - mnew);
        float psum = 0.f;
#pragma unroll
        for (int kk = 0; kk < 8; kk++) {
            float p = __expf(s8[kk] - mnew);
            Ps[r][lane + kk*16] = p;
            psum += p;
        }
#pragma unroll
        for (int off = 8; off > 0; off >>= 1)
            psum += __shfl_xor_sync(0xffffffffu, psum, off);
        lsum = lsum * corr + psum;
        m = mnew;
        if (lane == 0) corrs[r] = corr;
        __syncthreads();

        // PV: 2 rows x 2 dims per thread; float4 Ps loads, even/odd key chains preserved
        if (pv_on) {
#pragma unroll
            for (int q = 0; q < 2; q++) {
                float cc = corrs[pr0 + q];
                oa[q][0] *= cc; oa[q][1] *= cc;
                ob[q][0] *= cc; ob[q][1] *= cc;
            }
#pragma unroll
            for (int key = 0; key < 128; key += 4) {
                float2 v0 = *reinterpret_cast<const float2*>(&Vs[key][pd0]);
                float2 v1 = *reinterpret_cast<const float2*>(&Vs[key+1][pd0]);
                float2 v2 = *reinterpret_cast<const float2*>(&Vs[key+2][pd0]);
                float2 v3 = *reinterpret_cast<const float2*>(&Vs[key+3][pd0]);
#pragma unroll
                for (int q = 0; q < 2; q++) {
                    float4 p = *reinterpret_cast<const float4*>(&Ps[pr0+q][key]);
                    oa[q][0] += p.x*v0.x; oa[q][1] += p.x*v0.y;
                    ob[q][0] += p.y*v1.x; ob[q][1] += p.y*v1.y;
                    oa[q][0] += p.z*v2.x; oa[q][1] += p.z*v2.y;
                    ob[q][0] += p.w*v3.x; ob[q][1] += p.w*v3.y;
                }
            }
        }
    }
    if (lane == 0) invs[r] = 1.f / lsum;
    __syncthreads();
    if (pv_on) {
#pragma unroll
        for (int q = 0; q < 2; q++) {
            int row = pr0 + q;
            float inv = invs[row];
            float* dst = &g_att[(q0+row)*DS_ + hd + pd0];
            dst[0] = (oa[q][0] + ob[q][0]) * inv;
            dst[1] = (oa[q][1] + ob[q][1]) * inv;
        }
    }
}

// ---------------- fused d + e (+ kv for l==0): 128 blocks x 8 rows ----------------
__global__ void __launch_bounds__(512)
k_del(int l, int par, const float* __restrict__ bo, const float* __restrict__ bkv) {
    __shared__ __align__(16) float Att[8][128];
    __shared__ __align__(16) float Wc[32][128];
    __shared__ __align__(16) float Hn[8][128];
    __shared__ __align__(16) float Xs[8][256];
    __shared__ short qlo[8][128]; __shared__ int cnto[8];
    __shared__ short qln[8][128]; __shared__ int cntn[8];
    __shared__ short qlx[8][256]; __shared__ int cntx[8];
    __shared__ int sred[512];
    const int tid = threadIdx.x;
    const int row0 = blockIdx.x * 8;
    const int wrp = tid >> 5, lane = tid & 31;
    const float* hsrc = g_hbuf[l][par];
    float* hdst = g_hbuf[l][1 - par];

    if (tid < 256) {
        int rr = tid >> 5, c4 = (tid & 31) * 4;
        *reinterpret_cast<float4*>(&Att[rr][c4]) =
            *reinterpret_cast<const float4*>(g_att + (size_t)(row0+rr)*DS_ + c4);
    }
    if (wrp < 8) {
        int base = 0;
        const float* hr = hsrc + (size_t)(row0+wrp)*DS_;
#pragma unroll
        for (int c4 = 0; c4 < 4; c4++) {
            float v = hr[c4*32 + lane];
            unsigned mask = __ballot_sync(0xffffffffu, v != 0.f);
            if (v != 0.f)
                qlo[wrp][base + __popc(mask & ((1u<<lane)-1u))] = (short)(c4*32 + lane);
            base += __popc(mask);
        }
        if (lane == 0) cnto[wrp] = base;
    }

    const int r  = tid >> 6;
    const int cg = (tid & 63) * 2;
    float acc[2] = {};
    for (int kc = 0; kc < 4; kc++) {
        __syncthreads();
#pragma unroll
        for (int u = 0; u < 2; u++) {
            int i = tid + u*512;
            int k = i >> 5, c4b = (i & 31) * 4;
            *reinterpret_cast<float4*>(&Wc[k][c4b]) =
                *reinterpret_cast<const float4*>(g_Wot[l] + (size_t)(kc*32+k)*DS_ + c4b);
        }
        __syncthreads();
#pragma unroll
        for (int kk = 0; kk < 32; kk++) {
            float a = Att[r][kc*32 + kk];
            float2 wv = *reinterpret_cast<const float2*>(&Wc[kk][cg]);
            acc[0] += a*wv.x; acc[1] += a*wv.y;
        }
    }

    float thr = g_ts[l];
    int spikes = 0;
    {
        float st[2] = {};
        int cnt = cnto[r];
        const short* lst = qlo[r];
        const float* at = g_At[l] + cg;
        for (int i2 = 0; i2 < cnt; i2++) {
            float2 w = *reinterpret_cast<const float2*>(at + (int)lst[i2]*DS_);
            st[0] += w.x; st[1] += w.y;
        }
        int grow = (row0 + r)*DS_;
#pragma unroll
        for (int j = 0; j < 2; j++) {
            int ci = cg + j;
            float upd = acc[j] + bo[l*DS_ + ci] + st[j];
            float v = g_sv[l][grow + ci] * DECAY_F + upd;
            float sp = (v >= thr) ? 1.f : 0.f;
            hdst[grow + ci] = sp;
            Hn[r][ci] = sp;
            g_sv[l][grow + ci] = v * (1.f - sp);
            spikes += (v >= thr) ? 1 : 0;
        }
    }
    __syncthreads();

    if (wrp < 8) {
        int base = 0;
#pragma unroll
        for (int c4 = 0; c4 < 4; c4++) {
            float v = Hn[wrp][c4*32 + lane];
            unsigned mask = __ballot_sync(0xffffffffu, v != 0.f);
            if (v != 0.f)
                qln[wrp][base + __popc(mask & ((1u<<lane)-1u))] = (short)(c4*32 + lane);
            base += __popc(mask);
        }
        if (lane == 0) cntn[wrp] = base;
    }
    __syncthreads();

    const int c  = tid & 255;
    const int rh = (tid >> 8) * 4;
    const float* ct = g_Ct[l] + c;
    float thr2 = g_to[l];
    int spikes2 = 0;
#pragma unroll 1
    for (int r2 = rh; r2 < rh + 4; r2++) {
        float acc2 = 0.f;
        int cnt = cntn[r2];
        const short* lst = qln[r2];
        for (int i2 = 0; i2 < cnt; i2++)
            acc2 += ct[(int)lst[i2] * DM_];
        int gi = (row0 + r2)*DM_ + c;
        float v = g_ov[l][gi] * DECAY_F + acc2;
        float sp = (v >= thr2) ? 1.f : 0.f;
        g_ov[l][gi] = v * (1.f - sp);
        if (l == 0) { g_x[gi] = sp; Xs[r2][c] = sp; }
        else        { g_tsum[gi] += sp * 0.125f; }
        spikes2 += (v >= thr2) ? 1 : 0;
    }

    sred[tid] = spikes + (spikes2 << 16);
    __syncthreads();
    for (int s = 256; s > 0; s >>= 1) { if (tid < s) sred[tid] += sred[tid+s]; __syncthreads(); }
    if (tid == 0) {
        unsigned tot = (unsigned)sred[0];
        atomicAdd(&g_cnt1, tot & 0xffffu);
        atomicAdd(&g_cnt2, tot >> 16);
    }

    if (l == 0) {
        __syncthreads();
        if (wrp < 8) {
            int base = 0;
#pragma unroll
            for (int c4 = 0; c4 < 8; c4++) {
                float v = Xs[wrp][c4*32 + lane];
                unsigned mask = __ballot_sync(0xffffffffu, v != 0.f);
                if (v != 0.f)
                    qlx[wrp][base + __popc(mask & ((1u<<lane)-1u))] = (short)(c4*32 + lane);
                base += __popc(mask);
            }
            if (lane == 0) cntx[wrp] = base;
        }
        __syncthreads();
        const float* wt = g_Wkvt[1] + c;
        const float bias = bkv[2*DS_ + c];
#pragma unroll 1
        for (int r2 = rh; r2 < rh + 4; r2++) {
            float acc3 = 0.f;
            int cnt = cntx[r2];
            const short* lst = qlx[r2];
            for (int i2 = 0; i2 < cnt; i2++)
                acc3 += wt[(int)lst[i2] * (2*DS_)];
            g_kv[(row0 + r2)*(2*DS_) + c] = acc3 + bias;
        }
    }
}

// ---------------- logits via bf16 split tensor cores ----------------
__global__ void __launch_bounds__(256)
k_logits_mma(float* __restrict__ out) {
    __shared__ __align__(16) __nv_bfloat16 As[128][48];
    __shared__ __align__(16) __nv_bfloat16 Bs[128][48];
    const int tid = threadIdx.x;
    const int wid = tid >> 5;
    const int wm = wid & 1;
    const int wn = wid >> 1;
    const int row0 = blockIdx.x * 128;
    const int col0 = blockIdx.y * 128;

    wmma::fragment<wmma::accumulator, 16, 16, 16, float> acc[4][2];
#pragma unroll
    for (int i = 0; i < 4; i++)
#pragma unroll
        for (int j = 0; j < 2; j++)
            wmma::fill_fragment(acc[i][j], 0.f);

    const int lr = tid >> 1;
    const int lh = (tid & 1) * 16;

    for (int c = 0; c < 17; c++) {
        __nv_bfloat16 abuf[16];
        uint4 b0, b1;
        if (c < 16) {
            int koff = (c & 7) * 32;
            const float* af = g_tsum + (size_t)(row0+lr)*DM_ + koff + lh;
#pragma unroll
            for (int u = 0; u < 4; u++) {
                float4 f = *reinterpret_cast<const float4*>(af + u*4);
                abuf[u*4+0] = __float2bfloat16(f.x);
                abuf[u*4+1] = __float2bfloat16(f.y);
                abuf[u*4+2] = __float2bfloat16(f.z);
                abuf[u*4+3] = __float2bfloat16(f.w);
            }
            const __nv_bfloat16* bsrc = ((c < 8) ? g_Whi : g_Wlo) + (size_t)(col0+lr)*DM_ + koff + lh;
            b0 = *reinterpret_cast<const uint4*>(bsrc);
            b1 = *reinterpret_cast<const uint4*>(bsrc + 8);
        } else {
#pragma unroll
            for (int u = 0; u < 16; u++) abuf[u] = __float2bfloat16(0.f);
            if (lh == 0) { abuf[0] = __float2bfloat16(1.f); abuf[1] = __float2bfloat16(1.f); }
            const __nv_bfloat16* bsrc = g_Bext + (size_t)(col0+lr)*32 + lh;
            b0 = *reinterpret_cast<const uint4*>(bsrc);
            b1 = *reinterpret_cast<const uint4*>(bsrc + 8);
        }
        __syncthreads();
        *reinterpret_cast<uint4*>(&As[lr][lh])     = reinterpret_cast<uint4*>(abuf)[0];
        *reinterpret_cast<uint4*>(&As[lr][lh + 8]) = reinterpret_cast<uint4*>(abuf)[1];
        *reinterpret_cast<uint4*>(&Bs[lr][lh])     = b0;
        *reinterpret_cast<uint4*>(&Bs[lr][lh + 8]) = b1;
        __syncthreads();
#pragma unroll
        for (int kk = 0; kk < 32; kk += 16) {
            wmma::fragment<wmma::matrix_a, 16, 16, 16, __nv_bfloat16, wmma::row_major> af[4];
            wmma::fragment<wmma::matrix_b, 16, 16, 16, __nv_bfloat16, wmma::col_major> bf[2];
#pragma unroll
            for (int i = 0; i < 4; i++)
                wmma::load_matrix_sync(af[i], &As[wm*64 + i*16][kk], 48);
#pragma unroll
            for (int j = 0; j < 2; j++)
                wmma::load_matrix_sync(bf[j], &Bs[wn*32 + j*16][kk], 48);
#pragma unroll
            for (int i = 0; i < 4; i++)
#pragma unroll
                for (int j = 0; j < 2; j++)
                    wmma::mma_sync(acc[i][j], af[i], bf[j], acc[i][j]);
        }
    }
#pragma unroll
    for (int i = 0; i < 4; i++)
#pragma unroll
        for (int j = 0; j < 2; j++) {
            size_t r = row0 + wm*64 + i*16;
            size_t cc = col0 + wn*32 + j*16;
            wmma::store_matrix_sync(&out[r*VOC_ + cc], acc[i][j], VOC_, wmma::mem_row_major);
        }
}

// ---------------- launch ----------------
extern "C" void kernel_launch(void* const* d_in, const int* in_sizes, int n_in,
                              void* d_out, int out_size) {
    const int*   ids  = (const int*)d_in[0];
    const float* emb  = (const float*)d_in[1];
    const float* Amat = (const float*)d_in[2];
    const float* Cmat = (const float*)d_in[3];
    const float* Wq   = (const float*)d_in[4];
    const float* bq   = (const float*)d_in[5];
    const float* Wkv  = (const float*)d_in[6];
    const float* bkv  = (const float*)d_in[7];
    const float* Wo   = (const float*)d_in[8];
    const float* bo   = (const float*)d_in[9];
    const float* Wout = (const float*)d_in[10];
    const float* bout = (const float*)d_in[11];
    float* out = (float*)d_out;

    setup_kernel<<<2048, 256>>>(ids, emb, Wq, Amat, Wo, Cmat, Wkv, Wout, bout);
    k_kv0<<<dim3(4, 16), 512>>>(Wkv, bkv);
    k_rt<<<dim3(16, 4), 512>>>(0, bq);

    int prev = -1;
    for (int t = 0; t < T_; t++) {
        int par = t & 1;
        for (int l = 0; l < NL_; l++) {
            if (l == 1) k_rt<<<dim3(16, 4), 512>>>(1, bq);
            k_attn2<<<dim3(32, 4), 512>>>(l, prev, par);
            k_del  <<<128, 512>>>(l, par, bo, bkv);
            prev = l;
        }
    }
    k_logits_mma<<<dim3(8, 250), 256>>>(out);
}

// round 15
// speedup vs baseline: 1.0459x; 1.0459x over previous
#include <cuda_runtime.h>
#include <cuda_bf16.h>
#include <mma.h>
using namespace nvcuda;

#define BS_ 1024
#define DS_ 128
#define DM_ 256
#define NH_ 4
#define DH_ 32
#define T_ 8
#define NL_ 2
#define VOC_ 32000
#define DECAY_F 0.6065306597126334f
#define SCALE_F 0.17677669529663687f

// ---------------- device state ----------------
__device__ __align__(16) float g_tok[BS_*DM_];
__device__ __align__(16) float g_x[BS_*DM_];
__device__ __align__(16) float g_hbuf[NL_][2][BS_*DS_];
__device__ __align__(16) float g_sv[NL_][BS_*DS_];
__device__ __align__(16) float g_ov[NL_][BS_*DM_];
__device__ __align__(16) float g_kv0[BS_*2*DS_];
__device__ __align__(16) float g_kv[BS_*2*DS_];
__device__ __align__(16) float g_att[BS_*DS_];
__device__ __align__(16) float g_tsum[BS_*DM_];
// transposed weights
__device__ __align__(16) float g_Wqt[NL_][DS_*DS_];
__device__ __align__(16) float g_At [NL_][DS_*DS_];
__device__ __align__(16) float g_Wot[NL_][DS_*DS_];
__device__ __align__(16) float g_Ct [NL_][DS_*DM_];
__device__ __align__(16) float g_Wkvt[NL_][DM_*2*DS_];
__device__ float g_ts[NL_], g_to[NL_];
__device__ unsigned int g_cnt1, g_cnt2;

// score-factorization buffers: R[head][k][b], c[head][b]
__device__ __align__(16) float g_Rt0[NH_][DS_][BS_];
__device__ __align__(16) float g_Rt1[NH_][DS_][BS_];
__device__ float g_c0[NH_][BS_];
__device__ float g_c1[NH_][BS_];

// bf16 split storage for logits
__device__ __align__(16) __nv_bfloat16 g_Whi[(size_t)VOC_*DM_];
__device__ __align__(16) __nv_bfloat16 g_Wlo[(size_t)VOC_*DM_];
__device__ __align__(16) __nv_bfloat16 g_Bext[(size_t)VOC_*32];

// ---------------- fused setup ----------------
__global__ void setup_kernel(const int* __restrict__ ids, const float* __restrict__ emb,
                             const float* __restrict__ Wq, const float* __restrict__ Amat,
                             const float* __restrict__ Wo, const float* __restrict__ Cmat,
                             const float* __restrict__ Wkv,
                             const float* __restrict__ Wout, const float* __restrict__ bout) {
    int idx = blockIdx.x * blockDim.x + threadIdx.x;
    int stride = gridDim.x * blockDim.x;
    {
        float* h  = &g_hbuf[0][0][0];
        float* sv = &g_sv[0][0];
        float* ov = &g_ov[0][0];
        for (int i = idx; i < NL_*2*BS_*DS_; i += stride) h[i] = 0.f;
        for (int i = idx; i < NL_*BS_*DS_;  i += stride) sv[i] = 0.f;
        for (int i = idx; i < NL_*BS_*DM_;  i += stride) ov[i] = 0.f;
        for (int i = idx; i < BS_*DM_;      i += stride) g_tsum[i] = 0.f;
        if (idx == 0) {
            g_ts[0] = g_ts[1] = 1.0f;
            g_to[0] = g_to[1] = 1.0f;
            g_cnt1 = 0u; g_cnt2 = 0u;
        }
    }
    for (int i = idx; i < BS_*DM_; i += stride) {
        int row = i >> 8, j = i & 255;
        g_tok[i] = emb[(size_t)ids[row]*DM_ + j];
    }
    for (int i = idx; i < NL_*DS_*DS_; i += stride) {
        int l = i / (DS_*DS_), rem = i % (DS_*DS_);
        int k = rem / DS_, d = rem % DS_;
        g_Wqt[l][rem] = Wq[l*DS_*DS_ + d*DS_ + k];
        g_At [l][rem] = Amat[l*DS_*DS_ + d*DS_ + k];
        g_Wot[l][rem] = Wo[l*DS_*DS_ + d*DS_ + k];
    }
    for (int i = idx; i < NL_*DS_*DM_; i += stride) {
        int l = i / (DS_*DM_), rem = i % (DS_*DM_);
        int k = rem / DM_, c = rem % DM_;
        g_Ct[l][rem] = Cmat[l*DM_*DS_ + c*DS_ + k];
    }
    for (int i = idx; i < NL_*DM_*2*DS_; i += stride) {
        int l = i / (DM_*2*DS_), rem = i % (DM_*2*DS_);
        int k = rem / (2*DS_), c = rem % (2*DS_);
        g_Wkvt[l][rem] = Wkv[l*2*DS_*DM_ + c*DM_ + k];
    }
    {
        const int tot4 = VOC_ * DM_ / 4;
        for (int i = idx; i < tot4; i += stride) {
            float4 w = reinterpret_cast<const float4*>(Wout)[i];
            __nv_bfloat16 hb[4], lb[4];
            hb[0] = __float2bfloat16(w.x); lb[0] = __float2bfloat16(w.x - __bfloat162float(hb[0]));
            hb[1] = __float2bfloat16(w.y); lb[1] = __float2bfloat16(w.y - __bfloat162float(hb[1]));
            hb[2] = __float2bfloat16(w.z); lb[2] = __float2bfloat16(w.z - __bfloat162float(hb[2]));
            hb[3] = __float2bfloat16(w.w); lb[3] = __float2bfloat16(w.w - __bfloat162float(hb[3]));
            reinterpret_cast<uint2*>(g_Whi)[i] = *reinterpret_cast<uint2*>(hb);
            reinterpret_cast<uint2*>(g_Wlo)[i] = *reinterpret_cast<uint2*>(lb);
        }
        for (int n = idx; n < VOC_; n += stride) {
            float b = bout[n];
            __nv_bfloat16 buf[16];
            buf[0] = __float2bfloat16(b);
            buf[1] = __float2bfloat16(b - __bfloat162float(buf[0]));
#pragma unroll
            for (int c = 2; c < 16; c++) buf[c] = __float2bfloat16(0.f);
            uint4* dst = reinterpret_cast<uint4*>(&g_Bext[(size_t)n*32]);
            dst[0] = reinterpret_cast<uint4*>(buf)[0];
            dst[1] = reinterpret_cast<uint4*>(buf)[1];
            uint4 z; z.x = z.y = z.z = z.w = 0u;
            dst[2] = z; dst[3] = z;
        }
    }
}

// ---------------- dense kv for layer 0 (once) ----------------
__global__ void __launch_bounds__(512)
k_kv0(const float* __restrict__ Wkv, const float* __restrict__ bkv) {
    __shared__ __align__(16) float As[16][64];
    __shared__ __align__(16) float Ws[16][64];
    const int tid = threadIdx.x;
    const int row0 = blockIdx.y*64, col0 = blockIdx.x*64;
    const int ty = tid >> 4;
    const int tx = tid & 15;
    float acc[2][4] = {};
    for (int k0 = 0; k0 < DM_; k0 += 16) {
        if (tid < 256) {
            int lr = tid >> 2, lk = (tid & 3) << 2;
            float4 av = *reinterpret_cast<const float4*>(g_tok + (size_t)(row0+lr)*DM_ + k0 + lk);
            As[lk+0][lr]=av.x; As[lk+1][lr]=av.y; As[lk+2][lr]=av.z; As[lk+3][lr]=av.w;
        } else {
            int t2 = tid - 256;
            int lr = t2 >> 2, lk = (t2 & 3) << 2;
            float4 wv = *reinterpret_cast<const float4*>(Wkv + (size_t)(col0+lr)*DM_ + k0 + lk);
            Ws[lk+0][lr]=wv.x; Ws[lk+1][lr]=wv.y; Ws[lk+2][lr]=wv.z; Ws[lk+3][lr]=wv.w;
        }
        __syncthreads();
#pragma unroll
        for (int kk = 0; kk < 16; kk++) {
            float2 a = *reinterpret_cast<const float2*>(&As[kk][ty*2]);
            float4 w = *reinterpret_cast<const float4*>(&Ws[kk][tx*4]);
            acc[0][0]+=a.x*w.x; acc[0][1]+=a.x*w.y; acc[0][2]+=a.x*w.z; acc[0][3]+=a.x*w.w;
            acc[1][0]+=a.y*w.x; acc[1][1]+=a.y*w.y; acc[1][2]+=a.y*w.z; acc[1][3]+=a.y*w.w;
        }
        __syncthreads();
    }
#pragma unroll
    for (int i = 0; i < 2; i++) {
        int r = row0 + ty*2 + i;
#pragma unroll
        for (int j = 0; j < 4; j++) {
            int c = col0 + tx*4 + j;
            g_kv0[r*(2*DS_) + c] = acc[i][j] + bkv[c];
        }
    }
}

// ---------------- R factor ----------------
__global__ void __launch_bounds__(512)
k_rt(int l, const float* __restrict__ bq) {
    __shared__ __align__(16) float Ks[64][33];
    __shared__ __align__(16) float Wqs[32][128];
    const int tid = threadIdx.x;
    const int b0 = blockIdx.x * 64;
    const int head = blockIdx.y;
    const int hd = head * DH_;
    const float* kvsrc = (l == 0) ? g_kv0 : g_kv;
    float* Rt = (l == 0) ? &g_Rt0[head][0][0] : &g_Rt1[head][0][0];
    float* cv = (l == 0) ? g_c0[head] : g_c1[head];

    {
        int b = tid >> 3, d4 = (tid & 7) * 4;
        float4 v = *reinterpret_cast<const float4*>(kvsrc + (size_t)(b0+b)*(2*DS_) + hd + d4);
        Ks[b][d4] = v.x; Ks[b][d4+1] = v.y; Ks[b][d4+2] = v.z; Ks[b][d4+3] = v.w;
    }
    for (int i = tid; i < 32*128; i += 512) {
        int d = i >> 7, k = i & 127;
        Wqs[d][k] = g_Wqt[l][k*DS_ + hd + d];
    }
    __syncthreads();
    const int w = tid >> 5, lane = tid & 31;
    const int bloc = lane * 2;
    float acc[8][2] = {};
    for (int d = 0; d < 32; d++) {
        float kb0 = Ks[bloc][d], kb1 = Ks[bloc+1][d];
        const float* wq = &Wqs[d][w*8];
#pragma unroll
        for (int j = 0; j < 8; j++) {
            float q = wq[j];
            acc[j][0] += q * kb0;
            acc[j][1] += q * kb1;
        }
    }
#pragma unroll
    for (int j = 0; j < 8; j++) {
        float2 st = make_float2(acc[j][0], acc[j][1]);
        *reinterpret_cast<float2*>(Rt + (size_t)(w*8+j)*BS_ + b0 + bloc) = st;
    }
    if (tid < 64) {
        float cc = 0.f;
#pragma unroll
        for (int d = 0; d < 32; d++)
            cc += bq[l*DS_ + hd + d] * Ks[tid][d];
        cv[b0 + tid] = cc;
    }
}

// ---------------- attention: gathered scores (MLP x2) + concentrated PV (R13) ----------------
__global__ void __launch_bounds__(512)
k_attn2(int l, int prev_l, int par) {
    __shared__ __align__(16) float Vs[128][36];
    __shared__ __align__(16) float Ps[32][132];
    __shared__ float corrs[32], invs[32];
    __shared__ short ql[32][128];
    __shared__ int qcnt[32];
    const int tid = threadIdx.x;
    const int head = blockIdx.y;
    const int q0 = blockIdx.x * 32;
    const float* kvsrc = (l == 0) ? g_kv0 : g_kv;
    const float* hsrc = g_hbuf[l][par];
    const float* Rt = (l == 0) ? &g_Rt0[head][0][0] : &g_Rt1[head][0][0];
    const float* cv = (l == 0) ? g_c0[head] : g_c1[head];
    const int hd = head * DH_;

    if (prev_l >= 0 && blockIdx.x == 0 && blockIdx.y == 0 && tid == 0) {
        float e1 = (float)g_cnt1 / (float)(BS_*DS_) - 0.02f;
        g_ts[prev_l] = fmaxf(g_ts[prev_l] + 0.1f*e1, 0.5f);
        float e2 = (float)g_cnt2 / (float)(BS_*DM_) - 0.02f;
        g_to[prev_l] = fmaxf(g_to[prev_l] + 0.1f*e2, 0.5f);
        g_cnt1 = 0u; g_cnt2 = 0u;
    }

    // sparse lists: 16 warps x 2 rows
    {
        const int wrp = tid >> 5, lane = tid & 31;
#pragma unroll
        for (int rr = 0; rr < 2; rr++) {
            int r = wrp*2 + rr;
            int base = 0;
            const float* hr = hsrc + (size_t)(q0+r)*DS_;
#pragma unroll
            for (int c4 = 0; c4 < 4; c4++) {
                float v = hr[c4*32 + lane];
                unsigned mask = __ballot_sync(0xffffffffu, v != 0.f);
                if (v != 0.f)
                    ql[r][base + __popc(mask & ((1u<<lane)-1u))] = (short)(c4*32 + lane);
                base += __popc(mask);
            }
            if (lane == 0) qcnt[r] = base;
        }
    }
    __syncthreads();

    const int r = tid >> 4;            // softmax row
    const int lane = tid & 15;
    const int cnt = qcnt[r];

    // PV mapping: threads 0..127, 4 rows x 2 dims each
    const bool pv_on = (tid < 128);
    const int pr0 = (tid >> 4) * 4;
    const int pd0 = (tid & 15) * 2;

    float m = -INFINITY, lsum = 0.f;
    float oa[4][2] = {}, ob[4][2] = {};

    for (int kt = 0; kt < 8; kt++) {
        __syncthreads();
        // stage V: 128 rows x 32 dims
#pragma unroll
        for (int u = 0; u < 2; u++) {
            int i = tid + u*512;
            int kr = i >> 3, d4 = (i & 7) * 4;
            int key = kt*128 + kr;
            float4 v = *reinterpret_cast<const float4*>(kvsrc + (size_t)key*(2*DS_) + DS_ + hd + d4);
            Vs[kr][d4] = v.x; Vs[kr][d4+1] = v.y; Vs[kr][d4+2] = v.z; Vs[kr][d4+3] = v.w;
        }
        // gathered scores: 8 keys per lane; unroll-by-2 for MLP (order-preserving)
        const int kb = kt*128 + lane;
        float s8[8];
#pragma unroll
        for (int kk = 0; kk < 8; kk++) s8[kk] = cv[kb + kk*16];
        int i2 = 0;
        for (; i2 + 2 <= cnt; i2 += 2) {
            const float* rp0 = Rt + (size_t)ql[r][i2]*BS_ + kb;
            const float* rp1 = Rt + (size_t)ql[r][i2+1]*BS_ + kb;
            float a0[8], a1[8];
#pragma unroll
            for (int kk = 0; kk < 8; kk++) { a0[kk] = rp0[kk*16]; a1[kk] = rp1[kk*16]; }
#pragma unroll
            for (int kk = 0; kk < 8; kk++) { s8[kk] += a0[kk]; s8[kk] += a1[kk]; }
        }
        if (i2 < cnt) {
            const float* rp0 = Rt + (size_t)ql[r][i2]*BS_ + kb;
#pragma unroll
            for (int kk = 0; kk < 8; kk++) s8[kk] += rp0[kk*16];
        }
        // online softmax
        float tmax = -INFINITY;
#pragma unroll
        for (int kk = 0; kk < 8; kk++) { s8[kk] *= SCALE_F; tmax = fmaxf(tmax, s8[kk]); }
#pragma unroll
        for (int off = 8; off > 0; off >>= 1)
            tmax = fmaxf(tmax, __shfl_xor_sync(0xffffffffu, tmax, off));
        float mnew = fmaxf(m, tmax);
        float corr = __expf(m - mnew);
        float psum = 0.f;
#pragma unroll
        for (int kk = 0; kk < 8; kk++) {
            float p = __expf(s8[kk] - mnew);
            Ps[r][lane + kk*16] = p;
            psum += p;
        }
#pragma unroll
        for (int off = 8; off > 0; off >>= 1)
            psum += __shfl_xor_sync(0xffffffffu, psum, off);
        lsum = lsum * corr + psum;
        m = mnew;
        if (lane == 0) corrs[r] = corr;
        __syncthreads();

        // PV: 4 rows x 2 dims per thread; float4 Ps loads, even/odd key chains preserved
        if (pv_on) {
#pragma unroll
            for (int q = 0; q < 4; q++) {
                float cc = corrs[pr0 + q];
                oa[q][0] *= cc; oa[q][1] *= cc;
                ob[q][0] *= cc; ob[q][1] *= cc;
            }
#pragma unroll
            for (int key = 0; key < 128; key += 4) {
                float2 v0 = *reinterpret_cast<const float2*>(&Vs[key][pd0]);
                float2 v1 = *reinterpret_cast<const float2*>(&Vs[key+1][pd0]);
                float2 v2 = *reinterpret_cast<const float2*>(&Vs[key+2][pd0]);
                float2 v3 = *reinterpret_cast<const float2*>(&Vs[key+3][pd0]);
#pragma unroll
                for (int q = 0; q < 4; q++) {
                    float4 p = *reinterpret_cast<const float4*>(&Ps[pr0+q][key]);
                    oa[q][0] += p.x*v0.x; oa[q][1] += p.x*v0.y;
                    ob[q][0] += p.y*v1.x; ob[q][1] += p.y*v1.y;
                    oa[q][0] += p.z*v2.x; oa[q][1] += p.z*v2.y;
                    ob[q][0] += p.w*v3.x; ob[q][1] += p.w*v3.y;
                }
            }
        }
    }
    if (lane == 0) invs[r] = 1.f / lsum;
    __syncthreads();
    if (pv_on) {
#pragma unroll
        for (int q = 0; q < 4; q++) {
            int row = pr0 + q;
            float inv = invs[row];
            float* dst = &g_att[(q0+row)*DS_ + hd + pd0];
            dst[0] = (oa[q][0] + ob[q][0]) * inv;
            dst[1] = (oa[q][1] + ob[q][1]) * inv;
        }
    }
}

// ---------------- fused d + e (+ kv for l==0): 128 blocks x 8 rows ----------------
__global__ void __launch_bounds__(512)
k_del(int l, int par, const float* __restrict__ bo, const float* __restrict__ bkv) {
    __shared__ __align__(16) float Att[8][128];
    __shared__ __align__(16) float Wc[32][128];
    __shared__ __align__(16) float Hn[8][128];
    __shared__ __align__(16) float Xs[8][256];
    __shared__ short qlo[8][128]; __shared__ int cnto[8];
    __shared__ short qln[8][128]; __shared__ int cntn[8];
    __shared__ short qlx[8][256]; __shared__ int cntx[8];
    __shared__ int sred[512];
    const int tid = threadIdx.x;
    const int row0 = blockIdx.x * 8;
    const int wrp = tid >> 5, lane = tid & 31;
    const float* hsrc = g_hbuf[l][par];
    float* hdst = g_hbuf[l][1 - par];

    if (tid < 256) {
        int rr = tid >> 5, c4 = (tid & 31) * 4;
        *reinterpret_cast<float4*>(&Att[rr][c4]) =
            *reinterpret_cast<const float4*>(g_att + (size_t)(row0+rr)*DS_ + c4);
    }
    if (wrp < 8) {
        int base = 0;
        const float* hr = hsrc + (size_t)(row0+wrp)*DS_;
#pragma unroll
        for (int c4 = 0; c4 < 4; c4++) {
            float v = hr[c4*32 + lane];
            unsigned mask = __ballot_sync(0xffffffffu, v != 0.f);
            if (v != 0.f)
                qlo[wrp][base + __popc(mask & ((1u<<lane)-1u))] = (short)(c4*32 + lane);
            base += __popc(mask);
        }
        if (lane == 0) cnto[wrp] = base;
    }

    const int r  = tid >> 6;
    const int cg = (tid & 63) * 2;
    float acc[2] = {};
    for (int kc = 0; kc < 4; kc++) {
        __syncthreads();
#pragma unroll
        for (int u = 0; u < 2; u++) {
            int i = tid + u*512;
            int k = i >> 5, c4b = (i & 31) * 4;
            *reinterpret_cast<float4*>(&Wc[k][c4b]) =
                *reinterpret_cast<const float4*>(g_Wot[l] + (size_t)(kc*32+k)*DS_ + c4b);
        }
        __syncthreads();
#pragma unroll
        for (int kk = 0; kk < 32; kk++) {
            float a = Att[r][kc*32 + kk];
            float2 wv = *reinterpret_cast<const float2*>(&Wc[kk][cg]);
            acc[0] += a*wv.x; acc[1] += a*wv.y;
        }
    }

    float thr = g_ts[l];
    int spikes = 0;
    {
        float st[2] = {};
        int cnt = cnto[r];
        const short* lst = qlo[r];
        const float* at = g_At[l] + cg;
        int i2 = 0;
        for (; i2 + 2 <= cnt; i2 += 2) {
            float2 w0 = *reinterpret_cast<const float2*>(at + (int)lst[i2]*DS_);
            float2 w1 = *reinterpret_cast<const float2*>(at + (int)lst[i2+1]*DS_);
            st[0] += w0.x; st[1] += w0.y;
            st[0] += w1.x; st[1] += w1.y;
        }
        if (i2 < cnt) {
            float2 w0 = *reinterpret_cast<const float2*>(at + (int)lst[i2]*DS_);
            st[0] += w0.x; st[1] += w0.y;
        }
        int grow = (row0 + r)*DS_;
#pragma unroll
        for (int j = 0; j < 2; j++) {
            int ci = cg + j;
            float upd = acc[j] + bo[l*DS_ + ci] + st[j];
            float v = g_sv[l][grow + ci] * DECAY_F + upd;
            float sp = (v >= thr) ? 1.f : 0.f;
            hdst[grow + ci] = sp;
            Hn[r][ci] = sp;
            g_sv[l][grow + ci] = v * (1.f - sp);
            spikes += (v >= thr) ? 1 : 0;
        }
    }
    __syncthreads();

    if (wrp < 8) {
        int base = 0;
#pragma unroll
        for (int c4 = 0; c4 < 4; c4++) {
            float v = Hn[wrp][c4*32 + lane];
            unsigned mask = __ballot_sync(0xffffffffu, v != 0.f);
            if (v != 0.f)
                qln[wrp][base + __popc(mask & ((1u<<lane)-1u))] = (short)(c4*32 + lane);
            base += __popc(mask);
        }
        if (lane == 0) cntn[wrp] = base;
    }
    __syncthreads();

    const int c  = tid & 255;
    const int rh = (tid >> 8) * 4;
    const float* ct = g_Ct[l] + c;
    float thr2 = g_to[l];
    int spikes2 = 0;
#pragma unroll 1
    for (int r2 = rh; r2 < rh + 4; r2++) {
        float acc2 = 0.f;
        int cnt = cntn[r2];
        const short* lst = qln[r2];
        int i2 = 0;
        for (; i2 + 2 <= cnt; i2 += 2) {
            float a = ct[(int)lst[i2] * DM_];
            float b = ct[(int)lst[i2+1] * DM_];
            acc2 += a; acc2 += b;
        }
        if (i2 < cnt) acc2 += ct[(int)lst[i2] * DM_];
        int gi = (row0 + r2)*DM_ + c;
        float v = g_ov[l][gi] * DECAY_F + acc2;
        float sp = (v >= thr2) ? 1.f : 0.f;
        g_ov[l][gi] = v * (1.f - sp);
        if (l == 0) { g_x[gi] = sp; Xs[r2][c] = sp; }
        else        { g_tsum[gi] += sp * 0.125f; }
        spikes2 += (v >= thr2) ? 1 : 0;
    }

    sred[tid] = spikes + (spikes2 << 16);
    __syncthreads();
    for (int s = 256; s > 0; s >>= 1) { if (tid < s) sred[tid] += sred[tid+s]; __syncthreads(); }
    if (tid == 0) {
        unsigned tot = (unsigned)sred[0];
        atomicAdd(&g_cnt1, tot & 0xffffu);
        atomicAdd(&g_cnt2, tot >> 16);
    }

    if (l == 0) {
        __syncthreads();
        if (wrp < 8) {
            int base = 0;
#pragma unroll
            for (int c4 = 0; c4 < 8; c4++) {
                float v = Xs[wrp][c4*32 + lane];
                unsigned mask = __ballot_sync(0xffffffffu, v != 0.f);
                if (v != 0.f)
                    qlx[wrp][base + __popc(mask & ((1u<<lane)-1u))] = (short)(c4*32 + lane);
                base += __popc(mask);
            }
            if (lane == 0) cntx[wrp] = base;
        }
        __syncthreads();
        const float* wt = g_Wkvt[1] + c;
        const float bias = bkv[2*DS_ + c];
#pragma unroll 1
        for (int r2 = rh; r2 < rh + 4; r2++) {
            float acc3 = 0.f;
            int cnt = cntx[r2];
            const short* lst = qlx[r2];
            int i2 = 0;
            for (; i2 + 2 <= cnt; i2 += 2) {
                float a = wt[(int)lst[i2] * (2*DS_)];
                float b = wt[(int)lst[i2+1] * (2*DS_)];
                acc3 += a; acc3 += b;
            }
            if (i2 < cnt) acc3 += wt[(int)lst[i2] * (2*DS_)];
            g_kv[(row0 + r2)*(2*DS_) + c] = acc3 + bias;
        }
    }
}

// ---------------- logits via bf16 split tensor cores ----------------
__global__ void __launch_bounds__(256)
k_logits_mma(float* __restrict__ out) {
    __shared__ __align__(16) __nv_bfloat16 As[128][48];
    __shared__ __align__(16) __nv_bfloat16 Bs[128][48];
    const int tid = threadIdx.x;
    const int wid = tid >> 5;
    const int wm = wid & 1;
    const int wn = wid >> 1;
    const int row0 = blockIdx.x * 128;
    const int col0 = blockIdx.y * 128;

    wmma::fragment<wmma::accumulator, 16, 16, 16, float> acc[4][2];
#pragma unroll
    for (int i = 0; i < 4; i++)
#pragma unroll
        for (int j = 0; j < 2; j++)
            wmma::fill_fragment(acc[i][j], 0.f);

    const int lr = tid >> 1;
    const int lh = (tid & 1) * 16;

    for (int c = 0; c < 17; c++) {
        __nv_bfloat16 abuf[16];
        uint4 b0, b1;
        if (c < 16) {
            int koff = (c & 7) * 32;
            const float* af = g_tsum + (size_t)(row0+lr)*DM_ + koff + lh;
#pragma unroll
            for (int u = 0; u < 4; u++) {
                float4 f = *reinterpret_cast<const float4*>(af + u*4);
                abuf[u*4+0] = __float2bfloat16(f.x);
                abuf[u*4+1] = __float2bfloat16(f.y);
                abuf[u*4+2] = __float2bfloat16(f.z);
                abuf[u*4+3] = __float2bfloat16(f.w);
            }
            const __nv_bfloat16* bsrc = ((c < 8) ? g_Whi : g_Wlo) + (size_t)(col0+lr)*DM_ + koff + lh;
            b0 = *reinterpret_cast<const uint4*>(bsrc);
            b1 = *reinterpret_cast<const uint4*>(bsrc + 8);
        } else {
#pragma unroll
            for (int u = 0; u < 16; u++) abuf[u] = __float2bfloat16(0.f);
            if (lh == 0) { abuf[0] = __float2bfloat16(1.f); abuf[1] = __float2bfloat16(1.f); }
            const __nv_bfloat16* bsrc = g_Bext + (size_t)(col0+lr)*32 + lh;
            b0 = *reinterpret_cast<const uint4*>(bsrc);
            b1 = *reinterpret_cast<const uint4*>(bsrc + 8);
        }
        __syncthreads();
        *reinterpret_cast<uint4*>(&As[lr][lh])     = reinterpret_cast<uint4*>(abuf)[0];
        *reinterpret_cast<uint4*>(&As[lr][lh + 8]) = reinterpret_cast<uint4*>(abuf)[1];
        *reinterpret_cast<uint4*>(&Bs[lr][lh])     = b0;
        *reinterpret_cast<uint4*>(&Bs[lr][lh + 8]) = b1;
        __syncthreads();
#pragma unroll
        for (int kk = 0; kk < 32; kk += 16) {
            wmma::fragment<wmma::matrix_a, 16, 16, 16, __nv_bfloat16, wmma::row_major> af[4];
            wmma::fragment<wmma::matrix_b, 16, 16, 16, __nv_bfloat16, wmma::col_major> bf[2];
#pragma unroll
            for (int i = 0; i < 4; i++)
                wmma::load_matrix_sync(af[i], &As[wm*64 + i*16][kk], 48);
#pragma unroll
            for (int j = 0; j < 2; j++)
                wmma::load_matrix_sync(bf[j], &Bs[wn*32 + j*16][kk], 48);
#pragma unroll
            for (int i = 0; i < 4; i++)
#pragma unroll
                for (int j = 0; j < 2; j++)
                    wmma::mma_sync(acc[i][j], af[i], bf[j], acc[i][j]);
        }
    }
#pragma unroll
    for (int i = 0; i < 4; i++)
#pragma unroll
        for (int j = 0; j < 2; j++) {
            size_t r = row0 + wm*64 + i*16;
            size_t cc = col0 + wn*32 + j*16;
            wmma::store_matrix_sync(&out[r*VOC_ + cc], acc[i][j], VOC_, wmma::mem_row_major);
        }
}

// ---------------- launch ----------------
extern "C" void kernel_launch(void* const* d_in, const int* in_sizes, int n_in,
                              void* d_out, int out_size) {
    const int*   ids  = (const int*)d_in[0];
    const float* emb  = (const float*)d_in[1];
    const float* Amat = (const float*)d_in[2];
    const float* Cmat = (const float*)d_in[3];
    const float* Wq   = (const float*)d_in[4];
    const float* bq   = (const float*)d_in[5];
    const float* Wkv  = (const float*)d_in[6];
    const float* bkv  = (const float*)d_in[7];
    const float* Wo   = (const float*)d_in[8];
    const float* bo   = (const float*)d_in[9];
    const float* Wout = (const float*)d_in[10];
    const float* bout = (const float*)d_in[11];
    float* out = (float*)d_out;

    setup_kernel<<<2048, 256>>>(ids, emb, Wq, Amat, Wo, Cmat, Wkv, Wout, bout);
    k_kv0<<<dim3(4, 16), 512>>>(Wkv, bkv);
    k_rt<<<dim3(16, 4), 512>>>(0, bq);

    int prev = -1;
    for (int t = 0; t < T_; t++) {
        int par = t & 1;
        for (int l = 0; l < NL_; l++) {
            if (l == 1) k_rt<<<dim3(16, 4), 512>>>(1, bq);
            k_attn2<<<dim3(32, 4), 512>>>(l, prev, par);
            k_del  <<<128, 512>>>(l, par, bo, bkv);
            prev = l;
        }
    }
    k_logits_mma<<<dim3(8, 250), 256>>>(out);
}

// round 16
// speedup vs baseline: 1.1388x; 1.0888x over previous
#include <cuda_runtime.h>
#include <cuda_bf16.h>
#include <mma.h>
using namespace nvcuda;

#define BS_ 1024
#define DS_ 128
#define DM_ 256
#define NH_ 4
#define DH_ 32
#define T_ 8
#define NL_ 2
#define VOC_ 32000
#define DECAY_F 0.6065306597126334f
#define SCALE_F 0.17677669529663687f

// ---------------- device state ----------------
__device__ __align__(16) float g_tok[BS_*DM_];
__device__ __align__(16) float g_x[BS_*DM_];
__device__ __align__(16) float g_hbuf[NL_][2][BS_*DS_];
__device__ __align__(16) float g_sv[NL_][BS_*DS_];
__device__ __align__(16) float g_ov[NL_][BS_*DM_];
__device__ __align__(16) float g_kv0[BS_*2*DS_];
__device__ __align__(16) float g_kv[BS_*2*DS_];
__device__ __align__(16) float g_att[BS_*DS_];
__device__ __align__(16) float g_tsum[BS_*DM_];
// transposed weights
__device__ __align__(16) float g_Wqt[NL_][DS_*DS_];
__device__ __align__(16) float g_At [NL_][DS_*DS_];
__device__ __align__(16) float g_Wot[NL_][DS_*DS_];
__device__ __align__(16) float g_Ct [NL_][DS_*DM_];
__device__ __align__(16) float g_Wkvt[NL_][DM_*2*DS_];
__device__ float g_ts[NL_], g_to[NL_];
__device__ unsigned int g_cnt1, g_cnt2;

// score-factorization buffers: R[head][k][b], c[head][b]
__device__ __align__(16) float g_Rt0[NH_][DS_][BS_];
__device__ __align__(16) float g_Rt1[NH_][DS_][BS_];
__device__ float g_c0[NH_][BS_];
__device__ float g_c1[NH_][BS_];

// bf16 split storage for logits
__device__ __align__(16) __nv_bfloat16 g_Whi[(size_t)VOC_*DM_];
__device__ __align__(16) __nv_bfloat16 g_Wlo[(size_t)VOC_*DM_];
__device__ __align__(16) __nv_bfloat16 g_Bext[(size_t)VOC_*32];

// ---------------- fused setup ----------------
__global__ void setup_kernel(const int* __restrict__ ids, const float* __restrict__ emb,
                             const float* __restrict__ Wq, const float* __restrict__ Amat,
                             const float* __restrict__ Wo, const float* __restrict__ Cmat,
                             const float* __restrict__ Wkv,
                             const float* __restrict__ Wout, const float* __restrict__ bout) {
    int idx = blockIdx.x * blockDim.x + threadIdx.x;
    int stride = gridDim.x * blockDim.x;
    {
        float* h  = &g_hbuf[0][0][0];
        float* sv = &g_sv[0][0];
        float* ov = &g_ov[0][0];
        for (int i = idx; i < NL_*2*BS_*DS_; i += stride) h[i] = 0.f;
        for (int i = idx; i < NL_*BS_*DS_;  i += stride) sv[i] = 0.f;
        for (int i = idx; i < NL_*BS_*DM_;  i += stride) ov[i] = 0.f;
        for (int i = idx; i < BS_*DM_;      i += stride) g_tsum[i] = 0.f;
        if (idx == 0) {
            g_ts[0] = g_ts[1] = 1.0f;
            g_to[0] = g_to[1] = 1.0f;
            g_cnt1 = 0u; g_cnt2 = 0u;
        }
    }
    for (int i = idx; i < BS_*DM_; i += stride) {
        int row = i >> 8, j = i & 255;
        g_tok[i] = emb[(size_t)ids[row]*DM_ + j];
    }
    for (int i = idx; i < NL_*DS_*DS_; i += stride) {
        int l = i / (DS_*DS_), rem = i % (DS_*DS_);
        int k = rem / DS_, d = rem % DS_;
        g_Wqt[l][rem] = Wq[l*DS_*DS_ + d*DS_ + k];
        g_At [l][rem] = Amat[l*DS_*DS_ + d*DS_ + k];
        g_Wot[l][rem] = Wo[l*DS_*DS_ + d*DS_ + k];
    }
    for (int i = idx; i < NL_*DS_*DM_; i += stride) {
        int l = i / (DS_*DM_), rem = i % (DS_*DM_);
        int k = rem / DM_, c = rem % DM_;
        g_Ct[l][rem] = Cmat[l*DM_*DS_ + c*DS_ + k];
    }
    for (int i = idx; i < NL_*DM_*2*DS_; i += stride) {
        int l = i / (DM_*2*DS_), rem = i % (DM_*2*DS_);
        int k = rem / (2*DS_), c = rem % (2*DS_);
        g_Wkvt[l][rem] = Wkv[l*2*DS_*DM_ + c*DM_ + k];
    }
    {
        const int tot4 = VOC_ * DM_ / 4;
        for (int i = idx; i < tot4; i += stride) {
            float4 w = reinterpret_cast<const float4*>(Wout)[i];
            __nv_bfloat16 hb[4], lb[4];
            hb[0] = __float2bfloat16(w.x); lb[0] = __float2bfloat16(w.x - __bfloat162float(hb[0]));
            hb[1] = __float2bfloat16(w.y); lb[1] = __float2bfloat16(w.y - __bfloat162float(hb[1]));
            hb[2] = __float2bfloat16(w.z); lb[2] = __float2bfloat16(w.z - __bfloat162float(hb[2]));
            hb[3] = __float2bfloat16(w.w); lb[3] = __float2bfloat16(w.w - __bfloat162float(hb[3]));
            reinterpret_cast<uint2*>(g_Whi)[i] = *reinterpret_cast<uint2*>(hb);
            reinterpret_cast<uint2*>(g_Wlo)[i] = *reinterpret_cast<uint2*>(lb);
        }
        for (int n = idx; n < VOC_; n += stride) {
            float b = bout[n];
            __nv_bfloat16 buf[16];
            buf[0] = __float2bfloat16(b);
            buf[1] = __float2bfloat16(b - __bfloat162float(buf[0]));
#pragma unroll
            for (int c = 2; c < 16; c++) buf[c] = __float2bfloat16(0.f);
            uint4* dst = reinterpret_cast<uint4*>(&g_Bext[(size_t)n*32]);
            dst[0] = reinterpret_cast<uint4*>(buf)[0];
            dst[1] = reinterpret_cast<uint4*>(buf)[1];
            uint4 z; z.x = z.y = z.z = z.w = 0u;
            dst[2] = z; dst[3] = z;
        }
    }
}

// ---------------- dense kv for layer 0 (once) ----------------
__global__ void __launch_bounds__(512)
k_kv0(const float* __restrict__ Wkv, const float* __restrict__ bkv) {
    __shared__ __align__(16) float As[16][64];
    __shared__ __align__(16) float Ws[16][64];
    const int tid = threadIdx.x;
    const int row0 = blockIdx.y*64, col0 = blockIdx.x*64;
    const int ty = tid >> 4;
    const int tx = tid & 15;
    float acc[2][4] = {};
    for (int k0 = 0; k0 < DM_; k0 += 16) {
        if (tid < 256) {
            int lr = tid >> 2, lk = (tid & 3) << 2;
            float4 av = *reinterpret_cast<const float4*>(g_tok + (size_t)(row0+lr)*DM_ + k0 + lk);
            As[lk+0][lr]=av.x; As[lk+1][lr]=av.y; As[lk+2][lr]=av.z; As[lk+3][lr]=av.w;
        } else {
            int t2 = tid - 256;
            int lr = t2 >> 2, lk = (t2 & 3) << 2;
            float4 wv = *reinterpret_cast<const float4*>(Wkv + (size_t)(col0+lr)*DM_ + k0 + lk);
            Ws[lk+0][lr]=wv.x; Ws[lk+1][lr]=wv.y; Ws[lk+2][lr]=wv.z; Ws[lk+3][lr]=wv.w;
        }
        __syncthreads();
#pragma unroll
        for (int kk = 0; kk < 16; kk++) {
            float2 a = *reinterpret_cast<const float2*>(&As[kk][ty*2]);
            float4 w = *reinterpret_cast<const float4*>(&Ws[kk][tx*4]);
            acc[0][0]+=a.x*w.x; acc[0][1]+=a.x*w.y; acc[0][2]+=a.x*w.z; acc[0][3]+=a.x*w.w;
            acc[1][0]+=a.y*w.x; acc[1][1]+=a.y*w.y; acc[1][2]+=a.y*w.z; acc[1][3]+=a.y*w.w;
        }
        __syncthreads();
    }
#pragma unroll
    for (int i = 0; i < 2; i++) {
        int r = row0 + ty*2 + i;
#pragma unroll
        for (int j = 0; j < 4; j++) {
            int c = col0 + tx*4 + j;
            g_kv0[r*(2*DS_) + c] = acc[i][j] + bkv[c];
        }
    }
}

// ---------------- R factor (layer 0 only; layer 1 fused into k_del) ----------------
__global__ void __launch_bounds__(512)
k_rt(int l, const float* __restrict__ bq) {
    __shared__ __align__(16) float Ks[64][33];
    __shared__ __align__(16) float Wqs[32][128];
    const int tid = threadIdx.x;
    const int b0 = blockIdx.x * 64;
    const int head = blockIdx.y;
    const int hd = head * DH_;
    const float* kvsrc = (l == 0) ? g_kv0 : g_kv;
    float* Rt = (l == 0) ? &g_Rt0[head][0][0] : &g_Rt1[head][0][0];
    float* cv = (l == 0) ? g_c0[head] : g_c1[head];

    {
        int b = tid >> 3, d4 = (tid & 7) * 4;
        float4 v = *reinterpret_cast<const float4*>(kvsrc + (size_t)(b0+b)*(2*DS_) + hd + d4);
        Ks[b][d4] = v.x; Ks[b][d4+1] = v.y; Ks[b][d4+2] = v.z; Ks[b][d4+3] = v.w;
    }
    for (int i = tid; i < 32*128; i += 512) {
        int d = i >> 7, k = i & 127;
        Wqs[d][k] = g_Wqt[l][k*DS_ + hd + d];
    }
    __syncthreads();
    const int w = tid >> 5, lane = tid & 31;
    const int bloc = lane * 2;
    float acc[8][2] = {};
    for (int d = 0; d < 32; d++) {
        float kb0 = Ks[bloc][d], kb1 = Ks[bloc+1][d];
        const float* wq = &Wqs[d][w*8];
#pragma unroll
        for (int j = 0; j < 8; j++) {
            float q = wq[j];
            acc[j][0] += q * kb0;
            acc[j][1] += q * kb1;
        }
    }
#pragma unroll
    for (int j = 0; j < 8; j++) {
        float2 st = make_float2(acc[j][0], acc[j][1]);
        *reinterpret_cast<float2*>(Rt + (size_t)(w*8+j)*BS_ + b0 + bloc) = st;
    }
    if (tid < 64) {
        float cc = 0.f;
#pragma unroll
        for (int d = 0; d < 32; d++)
            cc += bq[l*DS_ + hd + d] * Ks[tid][d];
        cv[b0 + tid] = cc;
    }
}

// ---------------- attention: gathered scores + concentrated PV (R13 verbatim) ----------------
__global__ void __launch_bounds__(512)
k_attn2(int l, int prev_l, int par) {
    __shared__ __align__(16) float Vs[128][36];
    __shared__ __align__(16) float Ps[32][132];
    __shared__ float corrs[32], invs[32];
    __shared__ short ql[32][128];
    __shared__ int qcnt[32];
    const int tid = threadIdx.x;
    const int head = blockIdx.y;
    const int q0 = blockIdx.x * 32;
    const float* kvsrc = (l == 0) ? g_kv0 : g_kv;
    const float* hsrc = g_hbuf[l][par];
    const float* Rt = (l == 0) ? &g_Rt0[head][0][0] : &g_Rt1[head][0][0];
    const float* cv = (l == 0) ? g_c0[head] : g_c1[head];
    const int hd = head * DH_;

    if (prev_l >= 0 && blockIdx.x == 0 && blockIdx.y == 0 && tid == 0) {
        float e1 = (float)g_cnt1 / (float)(BS_*DS_) - 0.02f;
        g_ts[prev_l] = fmaxf(g_ts[prev_l] + 0.1f*e1, 0.5f);
        float e2 = (float)g_cnt2 / (float)(BS_*DM_) - 0.02f;
        g_to[prev_l] = fmaxf(g_to[prev_l] + 0.1f*e2, 0.5f);
        g_cnt1 = 0u; g_cnt2 = 0u;
    }

    // sparse lists: 16 warps x 2 rows
    {
        const int wrp = tid >> 5, lane = tid & 31;
#pragma unroll
        for (int rr = 0; rr < 2; rr++) {
            int r = wrp*2 + rr;
            int base = 0;
            const float* hr = hsrc + (size_t)(q0+r)*DS_;
#pragma unroll
            for (int c4 = 0; c4 < 4; c4++) {
                float v = hr[c4*32 + lane];
                unsigned mask = __ballot_sync(0xffffffffu, v != 0.f);
                if (v != 0.f)
                    ql[r][base + __popc(mask & ((1u<<lane)-1u))] = (short)(c4*32 + lane);
                base += __popc(mask);
            }
            if (lane == 0) qcnt[r] = base;
        }
    }
    __syncthreads();

    const int r = tid >> 4;            // softmax row
    const int lane = tid & 15;
    const int cnt = qcnt[r];

    // PV mapping: threads 0..127, 4 rows x 2 dims each
    const bool pv_on = (tid < 128);
    const int pr0 = (tid >> 4) * 4;
    const int pd0 = (tid & 15) * 2;

    float m = -INFINITY, lsum = 0.f;
    float oa[4][2] = {}, ob[4][2] = {};

    for (int kt = 0; kt < 8; kt++) {
        __syncthreads();
        // stage V: 128 rows x 32 dims
#pragma unroll
        for (int u = 0; u < 2; u++) {
            int i = tid + u*512;
            int kr = i >> 3, d4 = (i & 7) * 4;
            int key = kt*128 + kr;
            float4 v = *reinterpret_cast<const float4*>(kvsrc + (size_t)key*(2*DS_) + DS_ + hd + d4);
            Vs[kr][d4] = v.x; Vs[kr][d4+1] = v.y; Vs[kr][d4+2] = v.z; Vs[kr][d4+3] = v.w;
        }
        // gathered scores: 8 keys per lane
        const int kb = kt*128 + lane;
        float s8[8];
#pragma unroll
        for (int kk = 0; kk < 8; kk++) s8[kk] = cv[kb + kk*16];
        for (int i2 = 0; i2 < cnt; i2++) {
            const float* rp = Rt + (size_t)ql[r][i2]*BS_ + kb;
#pragma unroll
            for (int kk = 0; kk < 8; kk++) s8[kk] += rp[kk*16];
        }
        // online softmax
        float tmax = -INFINITY;
#pragma unroll
        for (int kk = 0; kk < 8; kk++) { s8[kk] *= SCALE_F; tmax = fmaxf(tmax, s8[kk]); }
#pragma unroll
        for (int off = 8; off > 0; off >>= 1)
            tmax = fmaxf(tmax, __shfl_xor_sync(0xffffffffu, tmax, off));
        float mnew = fmaxf(m, tmax);
        float corr = __expf(m - mnew);
        float psum = 0.f;
#pragma unroll
        for (int kk = 0; kk < 8; kk++) {
            float p = __expf(s8[kk] - mnew);
            Ps[r][lane + kk*16] = p;
            psum += p;
        }
#pragma unroll
        for (int off = 8; off > 0; off >>= 1)
            psum += __shfl_xor_sync(0xffffffffu, psum, off);
        lsum = lsum * corr + psum;
        m = mnew;
        if (lane == 0) corrs[r] = corr;
        __syncthreads();

        // PV: 4 rows x 2 dims per thread; float4 Ps loads, even/odd key chains preserved
        if (pv_on) {
#pragma unroll
            for (int q = 0; q < 4; q++) {
                float cc = corrs[pr0 + q];
                oa[q][0] *= cc; oa[q][1] *= cc;
                ob[q][0] *= cc; ob[q][1] *= cc;
            }
#pragma unroll
            for (int key = 0; key < 128; key += 4) {
                float2 v0 = *reinterpret_cast<const float2*>(&Vs[key][pd0]);
                float2 v1 = *reinterpret_cast<const float2*>(&Vs[key+1][pd0]);
                float2 v2 = *reinterpret_cast<const float2*>(&Vs[key+2][pd0]);
                float2 v3 = *reinterpret_cast<const float2*>(&Vs[key+3][pd0]);
#pragma unroll
                for (int q = 0; q < 4; q++) {
                    float4 p = *reinterpret_cast<const float4*>(&Ps[pr0+q][key]);
                    oa[q][0] += p.x*v0.x; oa[q][1] += p.x*v0.y;
                    ob[q][0] += p.y*v1.x; ob[q][1] += p.y*v1.y;
                    oa[q][0] += p.z*v2.x; oa[q][1] += p.z*v2.y;
                    ob[q][0] += p.w*v3.x; ob[q][1] += p.w*v3.y;
                }
            }
        }
    }
    if (lane == 0) invs[r] = 1.f / lsum;
    __syncthreads();
    if (pv_on) {
#pragma unroll
        for (int q = 0; q < 4; q++) {
            int row = pr0 + q;
            float inv = invs[row];
            float* dst = &g_att[(q0+row)*DS_ + hd + pd0];
            dst[0] = (oa[q][0] + ob[q][0]) * inv;
            dst[1] = (oa[q][1] + ob[q][1]) * inv;
        }
    }
}

// ---------------- fused d + e (+ kv + R-factor for l==0): 128 blocks x 8 rows ----------------
__global__ void __launch_bounds__(512)
k_del(int l, int par, const float* __restrict__ bo, const float* __restrict__ bkv,
      const float* __restrict__ Wq, const float* __restrict__ bq) {
    __shared__ __align__(16) float Att[8][128];
    __shared__ __align__(16) float Wc[32][128];
    __shared__ __align__(16) float Hn[8][128];
    __shared__ __align__(16) float Xs[8][256];
    __shared__ __align__(16) float Kb[8][128];
    __shared__ short qlo[8][128]; __shared__ int cnto[8];
    __shared__ short qln[8][128]; __shared__ int cntn[8];
    __shared__ short qlx[8][256]; __shared__ int cntx[8];
    __shared__ int sred[512];
    const int tid = threadIdx.x;
    const int row0 = blockIdx.x * 8;
    const int wrp = tid >> 5, lane = tid & 31;
    const float* hsrc = g_hbuf[l][par];
    float* hdst = g_hbuf[l][1 - par];

    if (tid < 256) {
        int rr = tid >> 5, c4 = (tid & 31) * 4;
        *reinterpret_cast<float4*>(&Att[rr][c4]) =
            *reinterpret_cast<const float4*>(g_att + (size_t)(row0+rr)*DS_ + c4);
    }
    if (wrp < 8) {
        int base = 0;
        const float* hr = hsrc + (size_t)(row0+wrp)*DS_;
#pragma unroll
        for (int c4 = 0; c4 < 4; c4++) {
            float v = hr[c4*32 + lane];
            unsigned mask = __ballot_sync(0xffffffffu, v != 0.f);
            if (v != 0.f)
                qlo[wrp][base + __popc(mask & ((1u<<lane)-1u))] = (short)(c4*32 + lane);
            base += __popc(mask);
        }
        if (lane == 0) cnto[wrp] = base;
    }

    const int r  = tid >> 6;
    const int cg = (tid & 63) * 2;
    float acc[2] = {};
    for (int kc = 0; kc < 4; kc++) {
        __syncthreads();
#pragma unroll
        for (int u = 0; u < 2; u++) {
            int i = tid + u*512;
            int k = i >> 5, c4b = (i & 31) * 4;
            *reinterpret_cast<float4*>(&Wc[k][c4b]) =
                *reinterpret_cast<const float4*>(g_Wot[l] + (size_t)(kc*32+k)*DS_ + c4b);
        }
        __syncthreads();
#pragma unroll
        for (int kk = 0; kk < 32; kk++) {
            float a = Att[r][kc*32 + kk];
            float2 wv = *reinterpret_cast<const float2*>(&Wc[kk][cg]);
            acc[0] += a*wv.x; acc[1] += a*wv.y;
        }
    }

    float thr = g_ts[l];
    int spikes = 0;
    {
        float st[2] = {};
        int cnt = cnto[r];
        const short* lst = qlo[r];
        const float* at = g_At[l] + cg;
        for (int i2 = 0; i2 < cnt; i2++) {
            float2 w = *reinterpret_cast<const float2*>(at + (int)lst[i2]*DS_);
            st[0] += w.x; st[1] += w.y;
        }
        int grow = (row0 + r)*DS_;
#pragma unroll
        for (int j = 0; j < 2; j++) {
            int ci = cg + j;
            float upd = acc[j] + bo[l*DS_ + ci] + st[j];
            float v = g_sv[l][grow + ci] * DECAY_F + upd;
            float sp = (v >= thr) ? 1.f : 0.f;
            hdst[grow + ci] = sp;
            Hn[r][ci] = sp;
            g_sv[l][grow + ci] = v * (1.f - sp);
            spikes += (v >= thr) ? 1 : 0;
        }
    }
    __syncthreads();

    if (wrp < 8) {
        int base = 0;
#pragma unroll
        for (int c4 = 0; c4 < 4; c4++) {
            float v = Hn[wrp][c4*32 + lane];
            unsigned mask = __ballot_sync(0xffffffffu, v != 0.f);
            if (v != 0.f)
                qln[wrp][base + __popc(mask & ((1u<<lane)-1u))] = (short)(c4*32 + lane);
            base += __popc(mask);
        }
        if (lane == 0) cntn[wrp] = base;
    }
    __syncthreads();

    const int c  = tid & 255;
    const int rh = (tid >> 8) * 4;
    const float* ct = g_Ct[l] + c;
    float thr2 = g_to[l];
    int spikes2 = 0;
#pragma unroll 1
    for (int r2 = rh; r2 < rh + 4; r2++) {
        float acc2 = 0.f;
        int cnt = cntn[r2];
        const short* lst = qln[r2];
        for (int i2 = 0; i2 < cnt; i2++)
            acc2 += ct[(int)lst[i2] * DM_];
        int gi = (row0 + r2)*DM_ + c;
        float v = g_ov[l][gi] * DECAY_F + acc2;
        float sp = (v >= thr2) ? 1.f : 0.f;
        g_ov[l][gi] = v * (1.f - sp);
        if (l == 0) { g_x[gi] = sp; Xs[r2][c] = sp; }
        else        { g_tsum[gi] += sp * 0.125f; }
        spikes2 += (v >= thr2) ? 1 : 0;
    }

    sred[tid] = spikes + (spikes2 << 16);
    __syncthreads();
    for (int s = 256; s > 0; s >>= 1) { if (tid < s) sred[tid] += sred[tid+s]; __syncthreads(); }
    if (tid == 0) {
        unsigned tot = (unsigned)sred[0];
        atomicAdd(&g_cnt1, tot & 0xffffu);
        atomicAdd(&g_cnt2, tot >> 16);
    }

    // kv gather + fused R-factor for layer 1 (only after l==0 step)
    if (l == 0) {
        __syncthreads();
        if (wrp < 8) {
            int base = 0;
#pragma unroll
            for (int c4 = 0; c4 < 8; c4++) {
                float v = Xs[wrp][c4*32 + lane];
                unsigned mask = __ballot_sync(0xffffffffu, v != 0.f);
                if (v != 0.f)
                    qlx[wrp][base + __popc(mask & ((1u<<lane)-1u))] = (short)(c4*32 + lane);
                base += __popc(mask);
            }
            if (lane == 0) cntx[wrp] = base;
        }
        __syncthreads();
        const float* wt = g_Wkvt[1] + c;
        const float bias = bkv[2*DS_ + c];
#pragma unroll 1
        for (int r2 = rh; r2 < rh + 4; r2++) {
            float acc3 = 0.f;
            int cnt = cntx[r2];
            const short* lst = qlx[r2];
            for (int i2 = 0; i2 < cnt; i2++)
                acc3 += wt[(int)lst[i2] * (2*DS_)];
            float kvv = acc3 + bias;
            g_kv[(row0 + r2)*(2*DS_) + c] = kvv;
            if (c < DS_) Kb[r2][c] = kvv;        // stage K-part for R factor
        }
        __syncthreads();

        // R factor: thread = (k, head); Rt1[head][k][row0+b] = sum_d Kb[b][hd+d]*Wq1[(hd+d)*DS+k]
        {
            const int k  = tid & 127;
            const int hh = tid >> 7;               // head 0..3
            const int hd2 = hh * DH_;
            const float* wq1 = Wq + (size_t)DS_*DS_;   // layer 1
            float accr[8] = {};
            for (int d = 0; d < 32; d++) {
                float wq = wq1[(size_t)(hd2 + d)*DS_ + k];
#pragma unroll
                for (int b = 0; b < 8; b++)
                    accr[b] += wq * Kb[b][hd2 + d];
            }
            float* dst = &g_Rt1[hh][k][row0];
            *reinterpret_cast<float4*>(dst)     = *reinterpret_cast<float4*>(&accr[0]);
            *reinterpret_cast<float4*>(dst + 4) = *reinterpret_cast<float4*>(&accr[4]);
        }
        // c1: threads 0..31 -> (head, b)
        if (tid < 32) {
            const int hh = tid >> 3, b = tid & 7;
            const int hd2 = hh * DH_;
            float cc = 0.f;
#pragma unroll
            for (int d = 0; d < 32; d++)
                cc += bq[DS_ + hd2 + d] * Kb[b][hd2 + d];
            g_c1[hh][row0 + b] = cc;
        }
    }
}

// ---------------- logits via bf16 split tensor cores ----------------
__global__ void __launch_bounds__(256)
k_logits_mma(float* __restrict__ out) {
    __shared__ __align__(16) __nv_bfloat16 As[128][48];
    __shared__ __align__(16) __nv_bfloat16 Bs[128][48];
    const int tid = threadIdx.x;
    const int wid = tid >> 5;
    const int wm = wid & 1;
    const int wn = wid >> 1;
    const int row0 = blockIdx.x * 128;
    const int col0 = blockIdx.y * 128;

    wmma::fragment<wmma::accumulator, 16, 16, 16, float> acc[4][2];
#pragma unroll
    for (int i = 0; i < 4; i++)
#pragma unroll
        for (int j = 0; j < 2; j++)
            wmma::fill_fragment(acc[i][j], 0.f);

    const int lr = tid >> 1;
    const int lh = (tid & 1) * 16;

    for (int c = 0; c < 17; c++) {
        __nv_bfloat16 abuf[16];
        uint4 b0, b1;
        if (c < 16) {
            int koff = (c & 7) * 32;
            const float* af = g_tsum + (size_t)(row0+lr)*DM_ + koff + lh;
#pragma unroll
            for (int u = 0; u < 4; u++) {
                float4 f = *reinterpret_cast<const float4*>(af + u*4);
                abuf[u*4+0] = __float2bfloat16(f.x);
                abuf[u*4+1] = __float2bfloat16(f.y);
                abuf[u*4+2] = __float2bfloat16(f.z);
                abuf[u*4+3] = __float2bfloat16(f.w);
            }
            const __nv_bfloat16* bsrc = ((c < 8) ? g_Whi : g_Wlo) + (size_t)(col0+lr)*DM_ + koff + lh;
            b0 = *reinterpret_cast<const uint4*>(bsrc);
            b1 = *reinterpret_cast<const uint4*>(bsrc + 8);
        } else {
#pragma unroll
            for (int u = 0; u < 16; u++) abuf[u] = __float2bfloat16(0.f);
            if (lh == 0) { abuf[0] = __float2bfloat16(1.f); abuf[1] = __float2bfloat16(1.f); }
            const __nv_bfloat16* bsrc = g_Bext + (size_t)(col0+lr)*32 + lh;
            b0 = *reinterpret_cast<const uint4*>(bsrc);
            b1 = *reinterpret_cast<const uint4*>(bsrc + 8);
        }
        __syncthreads();
        *reinterpret_cast<uint4*>(&As[lr][lh])     = reinterpret_cast<uint4*>(abuf)[0];
        *reinterpret_cast<uint4*>(&As[lr][lh + 8]) = reinterpret_cast<uint4*>(abuf)[1];
        *reinterpret_cast<uint4*>(&Bs[lr][lh])     = b0;
        *reinterpret_cast<uint4*>(&Bs[lr][lh + 8]) = b1;
        __syncthreads();
#pragma unroll
        for (int kk = 0; kk < 32; kk += 16) {
            wmma::fragment<wmma::matrix_a, 16, 16, 16, __nv_bfloat16, wmma::row_major> af[4];
            wmma::fragment<wmma::matrix_b, 16, 16, 16, __nv_bfloat16, wmma::col_major> bf[2];
#pragma unroll
            for (int i = 0; i < 4; i++)
                wmma::load_matrix_sync(af[i], &As[wm*64 + i*16][kk], 48);
#pragma unroll
            for (int j = 0; j < 2; j++)
                wmma::load_matrix_sync(bf[j], &Bs[wn*32 + j*16][kk], 48);
#pragma unroll
            for (int i = 0; i < 4; i++)
#pragma unroll
                for (int j = 0; j < 2; j++)
                    wmma::mma_sync(acc[i][j], af[i], bf[j], acc[i][j]);
        }
    }
#pragma unroll
    for (int i = 0; i < 4; i++)
#pragma unroll
        for (int j = 0; j < 2; j++) {
            size_t r = row0 + wm*64 + i*16;
            size_t cc = col0 + wn*32 + j*16;
            wmma::store_matrix_sync(&out[r*VOC_ + cc], acc[i][j], VOC_, wmma::mem_row_major);
        }
}

// ---------------- launch ----------------
extern "C" void kernel_launch(void* const* d_in, const int* in_sizes, int n_in,
                              void* d_out, int out_size) {
    const int*   ids  = (const int*)d_in[0];
    const float* emb  = (const float*)d_in[1];
    const float* Amat = (const float*)d_in[2];
    const float* Cmat = (const float*)d_in[3];
    const float* Wq   = (const float*)d_in[4];
    const float* bq   = (const float*)d_in[5];
    const float* Wkv  = (const float*)d_in[6];
    const float* bkv  = (const float*)d_in[7];
    const float* Wo   = (const float*)d_in[8];
    const float* bo   = (const float*)d_in[9];
    const float* Wout = (const float*)d_in[10];
    const float* bout = (const float*)d_in[11];
    float* out = (float*)d_out;

    setup_kernel<<<2048, 256>>>(ids, emb, Wq, Amat, Wo, Cmat, Wkv, Wout, bout);
    k_kv0<<<dim3(4, 16), 512>>>(Wkv, bkv);
    k_rt<<<dim3(16, 4), 512>>>(0, bq);

    int prev = -1;
    for (int t = 0; t < T_; t++) {
        int par = t & 1;
        for (int l = 0; l < NL_; l++) {
            k_attn2<<<dim3(32, 4), 512>>>(l, prev, par);
            k_del  <<<128, 512>>>(l, par, bo, bkv, Wq, bq);
            prev = l;
        }
    }
    k_logits_mma<<<dim3(8, 250), 256>>>(out);
}